// round 9
// baseline (speedup 1.0000x reference)
#include <cuda_runtime.h>
#include <cstdint>

// DbrxRouter: x[T,H] fp32 @ W[E=16,H]^T -> logits; softmax -> top4 -> /sum(top4)
// Outputs concatenated float32: weights [T,4] then expert indices [T,4] (as float).
//
// Warp = 8 tokens x 16 experts (quarter-warp expert split: 8-lane group q owns
// experts 4q..4q+3). Halves W-L1-wavefronts per FMA vs TOK=4. x staged through
// a warp-private cp.async ring (8 stages, zero CTA barriers). 1-warp CTAs
// (32 thr) -> 1024 CTAs ~= 7/SM, near-perfect wave balance.

#define NE      16
#define TOK     8
#define EPQ     4
#define STAGES  8
#define CH4     16            // float4 per chunk per token (64 floats)

__device__ __forceinline__ void fma2(unsigned long long& d,
                                     unsigned long long a,
                                     unsigned long long b) {
    asm("fma.rn.f32x2 %0, %1, %2, %0;" : "+l"(d) : "l"(a), "l"(b));
}
__device__ __forceinline__ float lo_f(unsigned long long v) {
    return __uint_as_float((unsigned)(v & 0xffffffffull));
}
__device__ __forceinline__ float hi_f(unsigned long long v) {
    return __uint_as_float((unsigned)(v >> 32));
}
__device__ __forceinline__ void cp16(uint32_t dst, const void* src) {
    asm volatile("cp.async.cg.shared.global [%0], [%1], 16;"
                 :: "r"(dst), "l"(src) : "memory");
}

__global__ __launch_bounds__(32)
void router_kernel(const float* __restrict__ x, const float* __restrict__ w,
                   float* __restrict__ out, int T, int H4, int idx_off)
{
    // Warp-private x staging: [stage][token][CH4 float4] = 16 KB.
    __shared__ __align__(16) ulonglong2 xs[STAGES][TOK * CH4];

    const int lane = threadIdx.x & 31;
    const int qid  = lane >> 3;          // quarter: experts 4q..4q+3
    const int sub  = lane & 7;
    const int t0   = blockIdx.x * TOK;
    if (t0 >= T) return;

    const ulonglong2* __restrict__ x2 = reinterpret_cast<const ulonglong2*>(x);
    const ulonglong2* __restrict__ w2 = reinterpret_cast<const ulonglong2*>(w);
    const ulonglong2* __restrict__ wq = w2 + (size_t)qid * EPQ * H4;

    // Copy mapping: 4 cp16 ops per chunk; op k covers token slots {2k, 2k+1}.
    //   slot = 2k + (lane>>4), off = lane&15  -> 32 lanes = 512B per op.
    const int offc = lane & 15;
    const int hb   = lane >> 4;
    const ulonglong2* srcp[4];
    #pragma unroll
    for (int k = 0; k < 4; k++) {
        const int tok = min(t0 + 2 * k + hb, T - 1);
        srcp[k] = x2 + (size_t)tok * H4 + offc;
    }
    const uint32_t smem_base = (uint32_t)__cvta_generic_to_shared(&xs[0][0]);
    uint32_t dstp[4];
    #pragma unroll
    for (int k = 0; k < 4; k++)
        dstp[k] = smem_base + (uint32_t)(((2 * k + hb) * CH4 + offc) * 16);
    const uint32_t stage_bytes = TOK * CH4 * 16;   // 2048

    const int NCH = H4 / CH4;            // 96 chunks

    // Prologue: fill STAGES-1 stages.
    #pragma unroll
    for (int p = 0; p < STAGES - 1; ++p) {
        const uint32_t sb = (uint32_t)p * stage_bytes;
        #pragma unroll
        for (int k = 0; k < 4; k++)
            cp16(dstp[k] + sb, srcp[k] + p * CH4);
        asm volatile("cp.async.commit_group;" ::: "memory");
    }

    unsigned long long acc[TOK][EPQ];
    #pragma unroll
    for (int t = 0; t < TOK; t++)
        #pragma unroll
        for (int e = 0; e < EPQ; e++)
            acc[t][e] = 0ull;

    const ulonglong2* xsw = &xs[0][0];

    #pragma unroll 1
    for (int c = 0; c < NCH; ++c) {
        // Issue copy for chunk c+STAGES-1 (empty group keeps counts uniform).
        const int cf = c + STAGES - 1;
        if (cf < NCH) {
            const uint32_t sb = (uint32_t)(cf & (STAGES - 1)) * stage_bytes;
            #pragma unroll
            for (int k = 0; k < 4; k++)
                cp16(dstp[k] + sb, srcp[k] + cf * CH4);
        }
        asm volatile("cp.async.commit_group;" ::: "memory");
        asm volatile("cp.async.wait_group %0;" :: "n"(STAGES - 2) : "memory");
        __syncwarp();

        const ulonglong2* xc = xsw + (size_t)(c & (STAGES - 1)) * (TOK * CH4);
        #pragma unroll
        for (int j = 0; j < 2; ++j) {
            const int jo = j * 8 + sub;
            ulonglong2 a[TOK];
            #pragma unroll
            for (int t = 0; t < TOK; t++)
                a[t] = xc[t * CH4 + jo];
            const size_t i = (size_t)c * CH4 + jo;
            #pragma unroll
            for (int e = 0; e < EPQ; e++) {
                const ulonglong2 b = wq[(size_t)e * H4 + i];
                #pragma unroll
                for (int t = 0; t < TOK; t++) {
                    fma2(acc[t][e], a[t].x, b.x);
                    fma2(acc[t][e], a[t].y, b.y);
                }
            }
        }
    }

    // Collapse packed halves; reduce within each 8-lane quarter (xor 4,2,1).
    float lg[TOK][EPQ];
    #pragma unroll
    for (int t = 0; t < TOK; t++)
        #pragma unroll
        for (int e = 0; e < EPQ; e++)
            lg[t][e] = lo_f(acc[t][e]) + hi_f(acc[t][e]);

    #pragma unroll
    for (int off = 4; off >= 1; off >>= 1)
        #pragma unroll
        for (int t = 0; t < TOK; t++)
            #pragma unroll
            for (int e = 0; e < EPQ; e++)
                lg[t][e] += __shfl_xor_sync(0xffffffffu, lg[t][e], off);

    // Lane sub==t within each quarter holds token t's 4 quarter-local experts.
    float sel[EPQ];
    #pragma unroll
    for (int e = 0; e < EPQ; e++) {
        float v = lg[0][e];
        #pragma unroll
        for (int t = 1; t < TOK; t++)
            if (sub == t) v = lg[t][e];
        sel[e] = v;
    }

    // Lane l (<8) gathers token l's 16 experts from lanes {8q + l}.
    float mylg[NE];
    #pragma unroll
    for (int q = 0; q < 4; q++)
        #pragma unroll
        for (int e = 0; e < EPQ; e++)
            mylg[q * EPQ + e] = __shfl_sync(0xffffffffu, sel[e], q * 8 + sub);

    const int token = t0 + lane;
    if (lane < TOK && token < T) {
        // Top-4, stable (strict '>' picks lowest index on ties, matching jax).
        unsigned mask = 0;
        float tw[4];
        int   ti[4];
        #pragma unroll
        for (int k = 0; k < 4; k++) {
            float best = -3.402823466e38f;
            int bi = 0;
            #pragma unroll
            for (int e = 0; e < NE; e++) {
                bool ok = (((mask >> e) & 1u) == 0u) && (mylg[e] > best);
                if (ok) { best = mylg[e]; bi = e; }
            }
            tw[k] = best; ti[k] = bi;
            mask |= (1u << bi);
        }
        // Softmax denominator cancels against p=1 renorm.
        const float m = tw[0];
        float s = 0.f;
        #pragma unroll
        for (int k = 0; k < 4; k++) { tw[k] = expf(tw[k] - m); s += tw[k]; }
        const float inv = 1.0f / s;
        #pragma unroll
        for (int k = 0; k < 4; k++) {
            out[token * 4 + k] = tw[k] * inv;
            if (idx_off >= 0) out[idx_off + token * 4 + k] = (float)ti[k];
        }
    }
}

extern "C" void kernel_launch(void* const* d_in, const int* in_sizes, int n_in,
                              void* d_out, int out_size)
{
    const float* x = (const float*)d_in[0];
    const float* w = (const float*)d_in[1];

    const int H  = in_sizes[1] / NE;     // 6144
    const int T  = in_sizes[0] / H;      // 8192
    const int H4 = H / 4;                // 1536 float4 per row

    const int idx_off = (out_size >= T * 8) ? (T * 4) : -1;

    const int blocks = (T + TOK - 1) / TOK;   // 1024 one-warp CTAs
    router_kernel<<<blocks, 32>>>(x, w, (float*)d_out, T, H4, idx_off);
}

// round 12
// speedup vs baseline: 1.7530x; 1.7530x over previous
#include <cuda_runtime.h>
#include <cstdint>

// DbrxRouter: x[T,H] fp32 @ W[E=16,H]^T -> logits; softmax -> top4 -> /sum(top4)
// Outputs concatenated float32: weights [T,4] then indices [T,4] (as float).
//
// CTA = 128 thr / 4 warps / 16 tokens. Warp w: tokens 4w..4w+3; quarter q of a
// warp owns experts 4q..4q+3 (R8 layout). BOTH operands staged via cp.async
// rings: x per-CTA (16 tok x 256B/chunk) and W per-CTA (16 rows x 256B/chunk,
// shared by all warps -> W produced once, consumed from smem at 29cy, killing
// the W L2-miss stalls that bounded R8). 5-stage ring, 1 __syncthreads/chunk.

#define NE      16
#define TOK     4
#define EPQ     4
#define TOKC    16            // tokens per CTA
#define STAGES  5
#define PRO     3             // prologue depth (STAGES-2)
#define CH4     16            // float4 per row per chunk (256B)

__device__ __forceinline__ void fma2(unsigned long long& d,
                                     unsigned long long a,
                                     unsigned long long b) {
    asm("fma.rn.f32x2 %0, %1, %2, %0;" : "+l"(d) : "l"(a), "l"(b));
}
__device__ __forceinline__ float lo_f(unsigned long long v) {
    return __uint_as_float((unsigned)(v & 0xffffffffull));
}
__device__ __forceinline__ float hi_f(unsigned long long v) {
    return __uint_as_float((unsigned)(v >> 32));
}
__device__ __forceinline__ void cp16(uint32_t dst, const void* src) {
    asm volatile("cp.async.cg.shared.global [%0], [%1], 16;"
                 :: "r"(dst), "l"(src) : "memory");
}

__global__ __launch_bounds__(128, 4)
void router_kernel(const float* __restrict__ x, const float* __restrict__ w,
                   float* __restrict__ out, int T, int H4, int idx_off)
{
    // 5 x (4KB x + 4KB W) = 40KB static smem.
    __shared__ __align__(16) ulonglong2 xs[STAGES][TOKC][CH4];
    __shared__ __align__(16) ulonglong2 ws[STAGES][NE][CH4];

    const int tid  = threadIdx.x;
    const int wid  = tid >> 5;
    const int lane = tid & 31;
    const int qid  = lane >> 3;          // quarter: experts 4q..4q+3
    const int sub  = lane & 7;
    const int ct0  = blockIdx.x * TOKC;  // CTA's first token
    if (ct0 >= T) return;

    const ulonglong2* __restrict__ x2 = reinterpret_cast<const ulonglong2*>(x);
    const ulonglong2* __restrict__ w2 = reinterpret_cast<const ulonglong2*>(w);

    // ---- copy mapping: thread -> (row, off) and (row, off+8); 4 cp16/stage ----
    const int crow = tid >> 3;           // 0..15 (token slot / W row)
    const int coff = tid & 7;            // 0..7
    const ulonglong2* srcx = x2 + (size_t)min(ct0 + crow, T - 1) * H4 + coff;
    const ulonglong2* srcw = w2 + (size_t)crow * H4 + coff;

    const uint32_t xbase = (uint32_t)__cvta_generic_to_shared(&xs[0][0][0]);
    const uint32_t wbase = (uint32_t)__cvta_generic_to_shared(&ws[0][0][0]);
    const uint32_t stage_b = TOKC * CH4 * 16;            // 4096
    const uint32_t dx = xbase + (uint32_t)((crow * CH4 + coff) * 16);
    const uint32_t dw = wbase + (uint32_t)((crow * CH4 + coff) * 16);

    const int NCH = H4 / CH4;            // 96 chunks

    // Prologue: fill PRO stages.
    #pragma unroll
    for (int p = 0; p < PRO; ++p) {
        const uint32_t sb = (uint32_t)p * stage_b;
        cp16(dx + sb,            srcx + p * CH4);
        cp16(dx + sb + 8 * 16,   srcx + p * CH4 + 8);
        cp16(dw + sb,            srcw + p * CH4);
        cp16(dw + sb + 8 * 16,   srcw + p * CH4 + 8);
        asm volatile("cp.async.commit_group;" ::: "memory");
    }

    unsigned long long acc[TOK][EPQ];
    #pragma unroll
    for (int t = 0; t < TOK; t++)
        #pragma unroll
        for (int e = 0; e < EPQ; e++)
            acc[t][e] = 0ull;

    #pragma unroll 1
    for (int c = 0; c < NCH; ++c) {
        // Issue copies for chunk c+PRO (empty commit keeps group counts uniform).
        const int cf = c + PRO;
        if (cf < NCH) {
            const uint32_t sb = (uint32_t)(cf % STAGES) * stage_b;
            cp16(dx + sb,          srcx + cf * CH4);
            cp16(dx + sb + 8 * 16, srcx + cf * CH4 + 8);
            cp16(dw + sb,          srcw + cf * CH4);
            cp16(dw + sb + 8 * 16, srcw + cf * CH4 + 8);
        }
        asm volatile("cp.async.commit_group;" ::: "memory");
        asm volatile("cp.async.wait_group %0;" :: "n"(PRO - 1) : "memory");
        __syncthreads();   // all threads' chunk-c copies now visible

        const int st = c % STAGES;
        #pragma unroll
        for (int j = 0; j < 2; ++j) {
            const int jo = j * 8 + sub;
            const ulonglong2 a0 = xs[st][4 * wid + 0][jo];
            const ulonglong2 a1 = xs[st][4 * wid + 1][jo];
            const ulonglong2 a2 = xs[st][4 * wid + 2][jo];
            const ulonglong2 a3 = xs[st][4 * wid + 3][jo];
            #pragma unroll
            for (int e = 0; e < EPQ; e++) {
                const ulonglong2 b = ws[st][4 * qid + e][jo];
                fma2(acc[0][e], a0.x, b.x); fma2(acc[0][e], a0.y, b.y);
                fma2(acc[1][e], a1.x, b.x); fma2(acc[1][e], a1.y, b.y);
                fma2(acc[2][e], a2.x, b.x); fma2(acc[2][e], a2.y, b.y);
                fma2(acc[3][e], a3.x, b.x); fma2(acc[3][e], a3.y, b.y);
            }
        }
    }

    // Collapse packed halves; reduce within each 8-lane quarter (xor 4,2,1).
    float lg[TOK][EPQ];
    #pragma unroll
    for (int t = 0; t < TOK; t++)
        #pragma unroll
        for (int e = 0; e < EPQ; e++)
            lg[t][e] = lo_f(acc[t][e]) + hi_f(acc[t][e]);

    #pragma unroll
    for (int off = 4; off >= 1; off >>= 1)
        #pragma unroll
        for (int t = 0; t < TOK; t++)
            #pragma unroll
            for (int e = 0; e < EPQ; e++)
                lg[t][e] += __shfl_xor_sync(0xffffffffu, lg[t][e], off);

    // Lane sub==t within each quarter holds token t's 4 quarter-local experts.
    float sel[EPQ];
    #pragma unroll
    for (int e = 0; e < EPQ; e++) {
        float v = lg[0][e];
        if (sub == 1) v = lg[1][e];
        if (sub == 2) v = lg[2][e];
        if (sub == 3) v = lg[3][e];
        sel[e] = v;
    }

    // Lane l (<4) gathers token l's 16 experts from lanes {8q + l}.
    float mylg[NE];
    #pragma unroll
    for (int q = 0; q < 4; q++)
        #pragma unroll
        for (int e = 0; e < EPQ; e++)
            mylg[q * EPQ + e] = __shfl_sync(0xffffffffu, sel[e], q * 8 + (lane & 7));

    const int token = ct0 + 4 * wid + lane;
    if (lane < 4 && token < T) {
        // Top-4, stable (strict '>' picks lowest index on ties, matching jax).
        unsigned mask = 0;
        float tw[4];
        int   ti[4];
        #pragma unroll
        for (int k = 0; k < 4; k++) {
            float best = -3.402823466e38f;
            int bi = 0;
            #pragma unroll
            for (int e = 0; e < NE; e++) {
                bool ok = (((mask >> e) & 1u) == 0u) && (mylg[e] > best);
                if (ok) { best = mylg[e]; bi = e; }
            }
            tw[k] = best; ti[k] = bi;
            mask |= (1u << bi);
        }
        // Softmax denominator cancels against p=1 renorm.
        const float m = tw[0];
        float s = 0.f;
        #pragma unroll
        for (int k = 0; k < 4; k++) { tw[k] = expf(tw[k] - m); s += tw[k]; }
        const float inv = 1.0f / s;
        #pragma unroll
        for (int k = 0; k < 4; k++) {
            out[token * 4 + k] = tw[k] * inv;
            if (idx_off >= 0) out[idx_off + token * 4 + k] = (float)ti[k];
        }
    }
}

extern "C" void kernel_launch(void* const* d_in, const int* in_sizes, int n_in,
                              void* d_out, int out_size)
{
    const float* x = (const float*)d_in[0];
    const float* w = (const float*)d_in[1];

    const int H  = in_sizes[1] / NE;     // 6144
    const int T  = in_sizes[0] / H;      // 8192
    const int H4 = H / 4;                // 1536 float4 per row

    const int idx_off = (out_size >= T * 8) ? (T * 4) : -1;

    const int blocks = (T + TOKC - 1) / TOKC;   // 512 CTAs of 128 threads
    router_kernel<<<blocks, 128>>>(x, w, (float*)d_out, T, H4, idx_off);
}